// round 7
// baseline (speedup 1.0000x reference)
#include <cuda_runtime.h>
#include <stdint.h>
#include <limits.h>

// Problem scale (dataset fixed: T=2048, W=30, N=61440, k=819)
#define NMAX 61440
#define TMAX 2048
#define NT   1024

// global scratch (no allocations allowed)
__device__ unsigned long long g_bufA[NMAX];
__device__ unsigned long long g_bufB[NMAX];

__device__ __forceinline__ bool spans_cross(int s1, int e1, int s2, int e2) {
    return (s1 < s2 && s2 <= e1 && e1 < e2) || (s2 < s1 && s1 <= e2 && e2 < e1);
}

// ============================================================
// ONE kernel: key build -> 4-pass stable radix sort (block-wide)
//   -> greedy non-crossing selection -> bitonic finalize -> output.
// Single CTA, 1024 threads. All stage handoffs via __syncthreads.
// ============================================================
__global__ void __launch_bounds__(NT, 1)
k_all(const int* __restrict__ spans, const float* __restrict__ scores,
      const float* __restrict__ maskp, const int* __restrict__ pT,
      const int* __restrict__ pK, int N, float* __restrict__ out, int out_size)
{
    __shared__ union U {
        struct {                       // sort stage (~38 KB)
            unsigned wh[32][257];      // per-warp digit counts (padded vs bank conflicts)
            unsigned rb[256];          // running digit bases
            unsigned hist[4][256];     // 4 pass histograms -> exclusive bases
        } srt;
        struct {                       // greedy stage (~40 KB)
            int s2e[TMAX];             // start -> max end   (-1 unset)
            int e2s[TMAX];             // end   -> min start (INT_MAX unset)
            int se[NT];                // packed (s<<12|e) per chunk slot
            int cc[NT];                // candidate index per chunk slot
            int sList[NT];             // survivor thread ids (ordered)
            int accSE[NT];             // accepted packed spans (in accept order)
            unsigned long long acc[NT];// accepted sort keys for final output
        } gr;
    } u;
    __shared__ unsigned tmp8[8];
    __shared__ int wCnt[32], wOff[32];
    __shared__ int sh_cnt, sh_done, sh_S;

    const unsigned FULL = 0xFFFFFFFFu;
    int t = threadIdx.x, wp = t >> 5, ln = t & 31;
    unsigned ltm = (1u << ln) - 1u;

    // ---------------- Stage A: keys + all 4 histograms ----------------
    for (int j = t; j < 4 * 256; j += NT) ((unsigned*)u.srt.hist)[j] = 0;
    __syncthreads();

    for (int base = 0; base < N; base += NT) {
        int i = base + t;
        bool ok = (i < N);
        unsigned long long k = 0ull;
        if (ok) {
            float key = scores[i] + logf(maskp[i]);
            unsigned b   = __float_as_uint(key);
            unsigned asc = (b & 0x80000000u) ? ~b : (b | 0x80000000u);
            k = ((unsigned long long)(~asc) << 32) | (unsigned)i;
            g_bufA[i] = k;
        }
        #pragma unroll
        for (int p = 0; p < 4; p++) {
            unsigned d = ok ? (unsigned)((k >> (32 + 8 * p)) & 255u)
                            : (256u + (unsigned)ln);
            unsigned mm = __match_any_sync(FULL, d);
            if (ok && (mm & ltm) == 0u)
                atomicAdd(&u.srt.hist[p][d], (unsigned)__popc(mm));
        }
    }
    __syncthreads();

    // exclusive scan of each 256-bin histogram (in place)
    #pragma unroll
    for (int p = 0; p < 4; p++) {
        unsigned v = 0, x = 0;
        if (t < 256) {
            v = u.srt.hist[p][t]; x = v;
            #pragma unroll
            for (int o = 1; o < 32; o <<= 1) {
                unsigned y = __shfl_up_sync(FULL, x, o);
                if (ln >= o) x += y;
            }
            if (ln == 31) tmp8[t >> 5] = x;
        }
        __syncthreads();
        if (t < 8) {
            unsigned a = tmp8[t], orig = a;
            #pragma unroll
            for (int o = 1; o < 8; o <<= 1) {
                unsigned y = __shfl_up_sync(0xFFu, a, o);
                if (t >= o) a += y;
            }
            tmp8[t] = a - orig;
        }
        __syncthreads();
        if (t < 256) u.srt.hist[p][t] = (x - v) + tmp8[t >> 5];
        __syncthreads();
    }

    // ---------------- Stage B: 4 stable scatter passes ----------------
    for (int p = 0; p < 4; p++) {
        const unsigned long long* src = (p & 1) ? g_bufB : g_bufA;
        unsigned long long*       dst = (p & 1) ? g_bufA : g_bufB;
        int shift = 32 + 8 * p;
        if (t < 256) u.srt.rb[t] = u.srt.hist[p][t];
        __syncthreads();

        for (int base = 0; base < N; base += NT) {
            for (int j = t; j < 32 * 257; j += NT) ((unsigned*)u.srt.wh)[j] = 0;
            __syncthreads();

            int i = base + t;
            bool ok = (i < N);
            unsigned long long v = ok ? src[i] : 0ull;
            unsigned d = ok ? (unsigned)((v >> shift) & 255u) : (256u + (unsigned)ln);
            unsigned mm = __match_any_sync(FULL, d);
            int lr = __popc(mm & ltm);
            if (ok && lr == 0) u.srt.wh[wp][d] = (unsigned)__popc(mm);
            __syncthreads();

            // cross-warp exclusive scan per digit: warp wp owns digits [wp*8, wp*8+8)
            #pragma unroll
            for (int q = 0; q < 8; q++) {
                int dd = wp * 8 + q;
                unsigned val = u.srt.wh[ln][dd];
                unsigned s = val;
                #pragma unroll
                for (int o = 1; o < 32; o <<= 1) {
                    unsigned y = __shfl_up_sync(FULL, s, o);
                    if (ln >= o) s += y;
                }
                u.srt.wh[ln][dd] = u.srt.rb[dd] + s - val;
                if (ln == 31) u.srt.rb[dd] += s;
            }
            __syncthreads();

            if (ok) dst[u.srt.wh[wp][d] + lr] = v;   // stable scatter
            __syncthreads();
        }
    }
    // sorted order in g_bufA (A->B->A->B->A)

    // ---------------- Stage C: greedy non-crossing selection ----------------
    for (int i = t; i < TMAX; i += NT) { u.gr.s2e[i] = -1; u.gr.e2s[i] = INT_MAX; }
    if (t == 0) { sh_cnt = 0; sh_done = 0; }
    __syncthreads();

    int T = pT ? pT[0] : TMAX;
    int K = pK ? pK[0] : 819;
    int k_out = out_size / 5;          // layout: scores,k | idx,k | spans,2k | valid,k
    if (K > NT) K = NT;
    int nch = (N + NT - 1) / NT;

    for (int ch = 0; ch < nch; ch++) {
        if (sh_done) break;
        int cnt0 = sh_cnt;
        int i = ch * NT + t;
        bool maybe = false;
        int s = 0, e = 0, c = 0;
        if (i < N) {
            c = (int)(unsigned)(g_bufA[i] & 0xFFFFFFFFull);
            s = __ldg(&spans[2 * c]);
            e = __ldg(&spans[2 * c + 1]);
            if (cnt0 == 0) {
                maybe = true;                         // tables empty -> all survive
            } else {
                bool cross = false;
                int w = e - s;
                for (int d = 1; d <= w; d++)
                    if (u.gr.s2e[s + d] > e) { cross = true; break; }
                if (!cross)
                    for (int d = 0; d < w; d++)
                        if (u.gr.e2s[s + d] < s) { cross = true; break; }
                maybe = !cross;
            }
        }
        u.gr.se[t] = (s << 12) | e;
        u.gr.cc[t] = c;

        // ordered compaction of survivors
        unsigned bal = __ballot_sync(FULL, maybe);
        if (ln == 0) wCnt[wp] = __popc(bal);
        __syncthreads();
        if (t < 32) {
            int vv = wCnt[t], a2 = vv;
            #pragma unroll
            for (int o = 1; o < 32; o <<= 1) {
                int nb = __shfl_up_sync(FULL, a2, o);
                if (t >= o) a2 += nb;
            }
            wOff[t] = a2 - vv;
            if (t == 31) sh_S = a2;
        }
        __syncthreads();
        if (maybe) u.gr.sList[wOff[wp] + __popc(bal & ltm)] = t;
        __syncthreads();

        // phase-2: warp 0 resolves survivors serially-in-order
        if (t < 32) {
            int cnt = sh_cnt;
            int accStart = cnt;                      // accepts before this chunk
            int S = sh_S;
            for (int g = 0; g < S && cnt < K; g += 32) {
                int j = g + t;
                bool act = (j < S);
                int se1 = 0, c1 = 0;
                if (act) { int ti = u.gr.sList[j]; se1 = u.gr.se[ti]; c1 = u.gr.cc[ti]; }
                int s1 = se1 >> 12, e1 = se1 & 4095;
                bool alive = false;
                if (act) {
                    // re-check only vs in-chunk accepts (broadcast SMEM, pure ALU)
                    bool cross = false;
                    for (int a = accStart; a < cnt; a++) {
                        int p2 = u.gr.accSE[a];
                        if (spans_cross(s1, e1, p2 >> 12, p2 & 4095)) { cross = true; break; }
                    }
                    alive = !cross;
                }
                while (true) {
                    unsigned m = __ballot_sync(FULL, alive);
                    if (!m) break;
                    int lead = __ffs(m) - 1;
                    int pk2 = __shfl_sync(FULL, se1, lead);
                    int s2 = pk2 >> 12, e2 = pk2 & 4095;
                    if (t == lead) {
                        if (e2 > u.gr.s2e[s2]) u.gr.s2e[s2] = e2;
                        if (s2 < u.gr.e2s[e2]) u.gr.e2s[e2] = s2;
                        u.gr.accSE[cnt] = se1;
                        u.gr.acc[cnt] =
                            ((unsigned long long)(s1 * T + e1) << 17) | (unsigned)c1;
                        alive = false;
                    }
                    cnt++;                            // uniform across lanes
                    if (cnt >= K) alive = false;
                    else if (alive && spans_cross(s1, e1, s2, e2)) alive = false;
                    __syncwarp();
                }
            }
            if (t == 0) { sh_cnt = cnt; if (cnt >= K) sh_done = 1; }
        }
        __syncthreads();
    }

    // ---------------- Stage D: sort accepted by (s*T+e, idx), emit ----------------
    int cnt = sh_cnt;
    if (t >= cnt) u.gr.acc[t] = 0xFFFFFFFFFFFFFFFFull;
    __syncthreads();

    for (int ks = 2; ks <= NT; ks <<= 1) {
        for (int j = ks >> 1; j > 0; j >>= 1) {
            int ixj = t ^ j;
            if (ixj > t) {
                bool up = ((t & ks) == 0);
                unsigned long long a = u.gr.acc[t], b = u.gr.acc[ixj];
                if ((a > b) == up) { u.gr.acc[t] = b; u.gr.acc[ixj] = a; }
            }
            __syncthreads();
        }
    }

    int vcnt = (cnt < k_out) ? cnt : k_out;
    for (int j = t; j < k_out; j += NT) {
        bool valid = (j < vcnt);
        int c  = valid ? (int)(u.gr.acc[j] & 0x1FFFFull) : 0;
        float sc = valid ? scores[c] : 0.0f;
        int ss = valid ? spans[2 * c] : 0;
        int ee = valid ? spans[2 * c + 1] : 0;
        out[j]                     = sc;
        out[k_out + j]             = valid ? (float)c : 0.0f;
        out[2 * k_out + 2 * j]     = (float)ss;
        out[2 * k_out + 2 * j + 1] = (float)ee;
        out[4 * k_out + j]         = valid ? 1.0f : 0.0f;
    }
}

// ============================================================
extern "C" void kernel_launch(void* const* d_in, const int* in_sizes, int n_in,
                              void* d_out, int out_size) {
    const int*   spans  = (const int*)d_in[0];
    const float* scores = (const float*)d_in[1];
    const float* mask   = (const float*)d_in[2];
    const int*   pT     = (n_in > 3) ? (const int*)d_in[3] : nullptr;
    const int*   pK     = (n_in > 4) ? (const int*)d_in[4] : nullptr;
    int N = in_sizes[1];

    k_all<<<1, NT>>>(spans, scores, mask, pT, pK, N, (float*)d_out, out_size);
}

// round 8
// speedup vs baseline: 2.5073x; 2.5073x over previous
#include <cuda_runtime.h>
#include <stdint.h>
#include <limits.h>

// Problem scale (dataset fixed: T=2048, W=30, N=61440, k=819)
#define NMAX  61440
#define TMAX  2048
#define NB    60          // radix blocks; NB*CHUNK >= NMAX
#define CHUNK 1024
#define NT    1024

// ---- device-global scratch (no allocations allowed) ----
__device__ unsigned long long g_bufA[NMAX];
__device__ unsigned long long g_bufB[NMAX];
__device__ unsigned int       g_hist4[4][256 * NB];

__device__ __forceinline__ bool spans_cross(int s1, int e1, int s2, int e2) {
    return (s1 < s2 && s2 <= e1 && e1 < e2) || (s2 < s1 && s1 <= e2 && e2 < e1);
}

// ============================================================
// Kernel 1: build keys + histogram for PASS 0 + zero hists for passes 1..3.
// key64 = (~sortable_asc(score+log m)) << 32 | idx  (ascending sort = ref order)
// ============================================================
__global__ void __launch_bounds__(CHUNK, 1)
k_init_hist(const float* __restrict__ scores, const float* __restrict__ maskp, int N) {
    __shared__ unsigned h[256];
    int t = threadIdx.x, ln = t & 31;
    unsigned ltm = (1u << ln) - 1u;
    if (t < 256) h[t] = 0;
    __syncthreads();

    int i = blockIdx.x * CHUNK + t;
    bool ok = (i < N);
    unsigned d = 256u + (unsigned)ln;
    if (ok) {
        float key = scores[i] + logf(maskp[i]);
        unsigned b   = __float_as_uint(key);
        unsigned asc = (b & 0x80000000u) ? ~b : (b | 0x80000000u);
        unsigned long long k = ((unsigned long long)(~asc) << 32) | (unsigned)i;
        g_bufA[i] = k;
        d = (unsigned)((k >> 32) & 255u);
    }
    unsigned mm = __match_any_sync(0xFFFFFFFFu, d);
    if (ok && (mm & ltm) == 0u) atomicAdd(&h[d], (unsigned)__popc(mm));
    __syncthreads();

    if (t < 256) {
        g_hist4[0][t * NB + blockIdx.x] = h[t];
        // zero later-pass hist slices owned by this block
        g_hist4[1][t * NB + blockIdx.x] = 0;
        g_hist4[2][t * NB + blockIdx.x] = 0;
        g_hist4[3][t * NB + blockIdx.x] = 0;
    }
}

// ============================================================
// Scatter pass p: inline base computation from g_hist4[p], stable scatter,
// and (for p<3) accumulate pass p+1 per-destination-block histogram.
// 60 blocks x 256 threads, 4 waves of 256 per block.
// ============================================================
__global__ void __launch_bounds__(256, 1)
k_scatter(int p, int srcIsA, int N) {
    const unsigned long long* src = srcIsA ? g_bufA : g_bufB;
    unsigned long long*       dst = srcIsA ? g_bufB : g_bufA;
    int shift  = 32 + 8 * p;
    int shift2 = shift + 8;

    __shared__ unsigned base[256];
    __shared__ unsigned wh[8][256];
    __shared__ unsigned tmp8[8];
    int t  = threadIdx.x;
    int wp = t >> 5, ln = t & 31;
    unsigned ltm = (1u << ln) - 1u;
    const unsigned FULL = 0xFFFFFFFFu;

    // ---- inline scan: per-digit global base + this block's intra-digit offset ----
    unsigned pre = 0, tot = 0;
    {
        const unsigned* hp = &g_hist4[p][t * NB];
        int myb = blockIdx.x;
        #pragma unroll
        for (int b = 0; b < NB; b++) {
            unsigned c = __ldg(&hp[b]);
            pre += (b < myb) ? c : 0u;
            tot += c;
        }
    }
    // exclusive scan of tot across 256 digits (8 warps)
    unsigned x = tot;
    #pragma unroll
    for (int o = 1; o < 32; o <<= 1) {
        unsigned y = __shfl_up_sync(FULL, x, o);
        if (ln >= o) x += y;
    }
    if (ln == 31) tmp8[wp] = x;
    __syncthreads();
    if (t < 8) {
        unsigned a = tmp8[t], orig = a;
        #pragma unroll
        for (int o = 1; o < 8; o <<= 1) {
            unsigned y = __shfl_up_sync(0xFFu, a, o);
            if (t >= o) a += y;
        }
        tmp8[t] = a - orig;
    }
    __syncthreads();
    base[t] = (x - tot) + tmp8[wp] + pre;
    int cbase = blockIdx.x * CHUNK;

    // ---- 4 waves of stable scatter ----
    for (int wv = 0; wv < CHUNK / 256; wv++) {
        #pragma unroll
        for (int w = 0; w < 8; w++) wh[w][t] = 0;
        __syncthreads();

        int i = cbase + wv * 256 + t;
        bool ok = (i < N);
        unsigned long long v = ok ? src[i] : 0ull;
        unsigned d = ok ? (unsigned)((v >> shift) & 255u) : (256u + (unsigned)ln);
        unsigned mm = __match_any_sync(FULL, d);
        int lr = __popc(mm & ltm);
        if (ok && lr == 0) wh[wp][d] = (unsigned)__popc(mm);
        __syncthreads();

        // thread t owns digit t: exclusive prefix across 8 warps + base update
        unsigned run = base[t];
        #pragma unroll
        for (int w = 0; w < 8; w++) { unsigned c = wh[w][t]; wh[w][t] = run; run += c; }
        base[t] = run;
        __syncthreads();

        if (ok) {
            unsigned q = wh[wp][d] + (unsigned)lr;
            dst[q] = v;                              // stable scatter
            if (p < 3) {                             // feed next pass's histogram
                unsigned d2 = (unsigned)((v >> shift2) & 255u);
                atomicAdd(&g_hist4[p + 1][d2 * NB + (q >> 10)], 1u);
            }
        }
        __syncthreads();
    }
}

// ============================================================
// Greedy non-crossing selection + finalize (single CTA, 1024 threads).
// Phase-1: all threads prune chunk candidates vs live tables (monotone -> final).
// Phase-2: warp 0, groups of 32: step-A pairwise vs in-chunk accept list (ALU),
//          then leader-elect serial resolution (O(1)/accept).
// Finalize: bitonic sort of accepted keys by (s*T+e, idx), emit output.
// ============================================================
__global__ void __launch_bounds__(NT, 1)
k_greedy(const int* __restrict__ spans, const float* __restrict__ scores,
         const int* __restrict__ pT, const int* __restrict__ pK,
         int N, float* __restrict__ out, int out_size) {
    __shared__ int s2e[TMAX];          // start -> max end   (-1 unset)
    __shared__ int e2s[TMAX];          // end   -> min start (INT_MAX unset)
    __shared__ int seC[NT], cC[NT];
    __shared__ int sList[NT];
    __shared__ int accSE[NT];
    __shared__ unsigned long long acc[NT];
    __shared__ int wCnt[32], wOff[32];
    __shared__ int sh_cnt, sh_done, sh_S;

    const unsigned FULL = 0xFFFFFFFFu;
    int t = threadIdx.x, wp = t >> 5, ln = t & 31;
    unsigned ltm = (1u << ln) - 1u;

    for (int i = t; i < TMAX; i += NT) { s2e[i] = -1; e2s[i] = INT_MAX; }
    if (t == 0) { sh_cnt = 0; sh_done = 0; }
    __syncthreads();

    int T = pT ? pT[0] : TMAX;
    int K = pK ? pK[0] : 819;
    int k_out = out_size / 5;          // layout: scores,k | idx,k | spans,2k | valid,k
    if (K > NT) K = NT;
    int nch = (N + NT - 1) / NT;

    for (int ch = 0; ch < nch; ch++) {
        if (sh_done) break;
        int cnt0 = sh_cnt;
        int i = ch * NT + t;
        bool maybe = false;
        int s = 0, e = 0, c = 0;
        if (i < N) {
            c = (int)(unsigned)(g_bufA[i] & 0xFFFFFFFFull);
            s = __ldg(&spans[2 * c]);
            e = __ldg(&spans[2 * c + 1]);
            if (cnt0 == 0) {
                maybe = true;                          // tables empty
            } else {
                bool cross = false;
                int w = e - s;
                for (int d = 1; d <= w; d++)
                    if (s2e[s + d] > e) { cross = true; break; }
                if (!cross)
                    for (int d = 0; d < w; d++)
                        if (e2s[s + d] < s) { cross = true; break; }
                maybe = !cross;
            }
        }
        seC[t] = (s << 12) | e;
        cC[t]  = c;

        // ordered compaction of survivors
        unsigned bal = __ballot_sync(FULL, maybe);
        if (ln == 0) wCnt[wp] = __popc(bal);
        __syncthreads();
        if (t < 32) {
            int vv = wCnt[t], a2 = vv;
            #pragma unroll
            for (int o = 1; o < 32; o <<= 1) {
                int nb = __shfl_up_sync(FULL, a2, o);
                if (t >= o) a2 += nb;
            }
            wOff[t] = a2 - vv;
            if (t == 31) sh_S = a2;
        }
        __syncthreads();
        if (maybe) sList[wOff[wp] + __popc(bal & ltm)] = t;
        __syncthreads();

        // phase-2: warp 0 resolves survivors serially-in-order
        if (t < 32) {
            int cnt = sh_cnt;
            int accStart = cnt;
            int S = sh_S;
            for (int g = 0; g < S && cnt < K; g += 32) {
                int j = g + t;
                bool act = (j < S);
                int se1 = 0, c1 = 0;
                if (act) { int ti = sList[j]; se1 = seC[ti]; c1 = cC[ti]; }
                int s1 = se1 >> 12, e1 = se1 & 4095;
                bool alive = false;
                if (act) {
                    bool cross = false;
                    for (int a = accStart; a < cnt; a++) {   // in-chunk accepts only
                        int p2 = accSE[a];
                        if (spans_cross(s1, e1, p2 >> 12, p2 & 4095)) { cross = true; break; }
                    }
                    alive = !cross;
                }
                while (true) {
                    unsigned m = __ballot_sync(FULL, alive);
                    if (!m) break;
                    int lead = __ffs(m) - 1;
                    int pk2 = __shfl_sync(FULL, se1, lead);
                    int s2 = pk2 >> 12, e2 = pk2 & 4095;
                    if (t == lead) {
                        if (e2 > s2e[s2]) s2e[s2] = e2;
                        if (s2 < e2s[e2]) e2s[e2] = s2;
                        accSE[cnt] = se1;
                        acc[cnt] = ((unsigned long long)(s1 * T + e1) << 17) | (unsigned)c1;
                        alive = false;
                    }
                    cnt++;                                   // uniform
                    if (cnt >= K) alive = false;
                    else if (alive && spans_cross(s1, e1, s2, e2)) alive = false;
                }
                __syncwarp();   // make lead's SMEM writes visible to next group's step-A
            }
            if (t == 0) { sh_cnt = cnt; if (cnt >= K) sh_done = 1; }
        }
        __syncthreads();
    }

    // ---- finalize: sort accepted by (s*T+e, idx), emit ----
    int cnt = sh_cnt;
    if (t >= cnt) acc[t] = 0xFFFFFFFFFFFFFFFFull;
    __syncthreads();

    for (int ks = 2; ks <= NT; ks <<= 1) {
        for (int j = ks >> 1; j > 0; j >>= 1) {
            int ixj = t ^ j;
            if (ixj > t) {
                bool up = ((t & ks) == 0);
                unsigned long long a = acc[t], b = acc[ixj];
                if ((a > b) == up) { acc[t] = b; acc[ixj] = a; }
            }
            __syncthreads();
        }
    }

    int vcnt = (cnt < k_out) ? cnt : k_out;
    for (int j = t; j < k_out; j += NT) {
        bool valid = (j < vcnt);
        int c  = valid ? (int)(acc[j] & 0x1FFFFull) : 0;
        float sc = valid ? scores[c] : 0.0f;
        int ss = valid ? spans[2 * c] : 0;
        int ee = valid ? spans[2 * c + 1] : 0;
        out[j]                     = sc;
        out[k_out + j]             = valid ? (float)c : 0.0f;
        out[2 * k_out + 2 * j]     = (float)ss;
        out[2 * k_out + 2 * j + 1] = (float)ee;
        out[4 * k_out + j]         = valid ? 1.0f : 0.0f;
    }
}

// ============================================================
// Launch: 6 nodes total.
// ============================================================
extern "C" void kernel_launch(void* const* d_in, const int* in_sizes, int n_in,
                              void* d_out, int out_size) {
    const int*   spans  = (const int*)d_in[0];
    const float* scores = (const float*)d_in[1];
    const float* mask   = (const float*)d_in[2];
    const int*   pT     = (n_in > 3) ? (const int*)d_in[3] : nullptr;
    const int*   pK     = (n_in > 4) ? (const int*)d_in[4] : nullptr;
    int N = in_sizes[1];

    k_init_hist<<<NB, CHUNK>>>(scores, mask, N);
    k_scatter<<<NB, 256>>>(0, 1, N);   // A -> B
    k_scatter<<<NB, 256>>>(1, 0, N);   // B -> A
    k_scatter<<<NB, 256>>>(2, 1, N);   // A -> B
    k_scatter<<<NB, 256>>>(3, 0, N);   // B -> A  (sorted in g_bufA)
    k_greedy<<<1, NT>>>(spans, scores, pT, pK, N, (float*)d_out, out_size);
}

// round 9
// speedup vs baseline: 9.2059x; 3.6717x over previous
#include <cuda_runtime.h>
#include <stdint.h>
#include <limits.h>

// Problem scale (dataset fixed: T=2048, W=30, N=61440, k=819)
#define NMAX  61440
#define TMAX  2048
#define NB    60          // radix blocks; NB*CHUNK >= NMAX
#define CHUNK 1024
#define NT    1024

#define ST_UND 0
#define ST_ACC 1
#define ST_REJ 2

// ---- device-global scratch (no allocations allowed) ----
__device__ unsigned long long g_bufA[NMAX];
__device__ unsigned long long g_bufB[NMAX];
__device__ unsigned int       g_hist4[4][256 * NB];
__device__ unsigned long long g_acc[2048];   // accepted keys, candidate order

__device__ __forceinline__ bool spans_cross(int s1, int e1, int s2, int e2) {
    return (s1 < s2 && s2 <= e1 && e1 < e2) || (s2 < s1 && s1 <= e2 && e2 < e1);
}

// ============================================================
// Kernel 1: keys + pass-0 histogram + zero later-pass histograms.
// key64 = (~sortable_asc(score+log m)) << 32 | idx
// ============================================================
__global__ void __launch_bounds__(CHUNK, 1)
k_init_hist(const float* __restrict__ scores, const float* __restrict__ maskp, int N) {
    __shared__ unsigned h[256];
    int t = threadIdx.x, ln = t & 31;
    unsigned ltm = (1u << ln) - 1u;
    if (t < 256) h[t] = 0;
    __syncthreads();

    int i = blockIdx.x * CHUNK + t;
    bool ok = (i < N);
    unsigned d = 256u + (unsigned)ln;
    if (ok) {
        float key = scores[i] + logf(maskp[i]);
        unsigned b   = __float_as_uint(key);
        unsigned asc = (b & 0x80000000u) ? ~b : (b | 0x80000000u);
        unsigned long long k = ((unsigned long long)(~asc) << 32) | (unsigned)i;
        g_bufA[i] = k;
        d = (unsigned)((k >> 32) & 255u);
    }
    unsigned mm = __match_any_sync(0xFFFFFFFFu, d);
    if (ok && (mm & ltm) == 0u) atomicAdd(&h[d], (unsigned)__popc(mm));
    __syncthreads();

    if (t < 256) {
        g_hist4[0][t * NB + blockIdx.x] = h[t];
        g_hist4[1][t * NB + blockIdx.x] = 0;
        g_hist4[2][t * NB + blockIdx.x] = 0;
        g_hist4[3][t * NB + blockIdx.x] = 0;
    }
}

// ============================================================
// Scatter pass p: inline bases from g_hist4[p], stable scatter,
// accumulate next pass's per-destination-block histogram (p<3).
// ============================================================
__global__ void __launch_bounds__(256, 1)
k_scatter(int p, int srcIsA, int N) {
    const unsigned long long* src = srcIsA ? g_bufA : g_bufB;
    unsigned long long*       dst = srcIsA ? g_bufB : g_bufA;
    int shift  = 32 + 8 * p;
    int shift2 = shift + 8;

    __shared__ unsigned base[256];
    __shared__ unsigned wh[8][256];
    __shared__ unsigned tmp8[8];
    int t  = threadIdx.x;
    int wp = t >> 5, ln = t & 31;
    unsigned ltm = (1u << ln) - 1u;
    const unsigned FULL = 0xFFFFFFFFu;

    unsigned pre = 0, tot = 0;
    {
        const unsigned* hp = &g_hist4[p][t * NB];
        int myb = blockIdx.x;
        #pragma unroll
        for (int b = 0; b < NB; b++) {
            unsigned c = __ldg(&hp[b]);
            pre += (b < myb) ? c : 0u;
            tot += c;
        }
    }
    unsigned x = tot;
    #pragma unroll
    for (int o = 1; o < 32; o <<= 1) {
        unsigned y = __shfl_up_sync(FULL, x, o);
        if (ln >= o) x += y;
    }
    if (ln == 31) tmp8[wp] = x;
    __syncthreads();
    if (t < 8) {
        unsigned a = tmp8[t], orig = a;
        #pragma unroll
        for (int o = 1; o < 8; o <<= 1) {
            unsigned y = __shfl_up_sync(0xFFu, a, o);
            if (t >= o) a += y;
        }
        tmp8[t] = a - orig;
    }
    __syncthreads();
    base[t] = (x - tot) + tmp8[wp] + pre;
    int cbase = blockIdx.x * CHUNK;

    for (int wv = 0; wv < CHUNK / 256; wv++) {
        #pragma unroll
        for (int w = 0; w < 8; w++) wh[w][t] = 0;
        __syncthreads();

        int i = cbase + wv * 256 + t;
        bool ok = (i < N);
        unsigned long long v = ok ? src[i] : 0ull;
        unsigned d = ok ? (unsigned)((v >> shift) & 255u) : (256u + (unsigned)ln);
        unsigned mm = __match_any_sync(FULL, d);
        int lr = __popc(mm & ltm);
        if (ok && lr == 0) wh[wp][d] = (unsigned)__popc(mm);
        __syncthreads();

        unsigned run = base[t];
        #pragma unroll
        for (int w = 0; w < 8; w++) { unsigned c = wh[w][t]; wh[w][t] = run; run += c; }
        base[t] = run;
        __syncthreads();

        if (ok) {
            unsigned q = wh[wp][d] + (unsigned)lr;
            dst[q] = v;
            if (p < 3) {
                unsigned d2 = (unsigned)((v >> shift2) & 255u);
                atomicAdd(&g_hist4[p + 1][d2 * NB + (q >> 10)], 1u);
            }
        }
        __syncthreads();
    }
}

// ============================================================
// Greedy non-crossing selection: block-parallel fixed-point per chunk.
//   Prefilter: reject vs cross-chunk tables (monotone -> final).
//   Rounds: undecided t scans EARLIER survivors in 3 start-buckets:
//     cross ACCEPTED -> reject ; cross UNDECIDED -> wait ; none -> accept.
//   Accepted update tables (atomics) and append keys to g_acc in order.
// Finalize: first K accepts, bitonic by (s*T+e, idx), emit.
// ============================================================
__global__ void __launch_bounds__(NT, 1)
k_greedy(const int* __restrict__ spans, const float* __restrict__ scores,
         const int* __restrict__ pT, const int* __restrict__ pK,
         int N, float* __restrict__ out, int out_size) {
    __shared__ int s2e[TMAX];                 // start -> max end   (-1 unset)
    __shared__ int e2s[TMAX];                 // end   -> min start (INT_MAX unset)
    __shared__ int seC[NT];                   // packed (s<<12|e)
    __shared__ int cC[NT];                    // candidate id
    __shared__ int stateA[NT];
    __shared__ short bEntries[NT];            // survivor slots by bucket
    __shared__ int bCnt[64], bOff[64], bFill[64];
    __shared__ int wCnt[32], wOff[32];
    __shared__ unsigned long long sortbuf[NT];
    __shared__ int sh_cnt, sh_done;

    const unsigned FULL = 0xFFFFFFFFu;
    int t = threadIdx.x, wp = t >> 5, ln = t & 31;
    unsigned ltm = (1u << ln) - 1u;

    for (int i = t; i < TMAX; i += NT) { s2e[i] = -1; e2s[i] = INT_MAX; }
    if (t == 0) { sh_cnt = 0; sh_done = 0; }
    __syncthreads();

    int T = pT ? pT[0] : TMAX;
    int K = pK ? pK[0] : 819;
    int k_out = out_size / 5;                  // scores,k | idx,k | spans,2k | valid,k
    if (K > NT) K = NT;
    int nch = (N + NT - 1) / NT;

    for (int ch = 0; ch < nch; ch++) {
        if (sh_done) break;
        int cnt0 = sh_cnt;
        int i = ch * NT + t;
        int myState = ST_REJ;
        int s1 = 0, e1 = 0, c1 = 0;
        if (i < N) {
            c1 = (int)(unsigned)(g_bufA[i] & 0xFFFFFFFFull);
            s1 = __ldg(&spans[2 * c1]);
            e1 = __ldg(&spans[2 * c1 + 1]);
            if (cnt0 == 0) {
                myState = ST_UND;
            } else {
                bool cross = false;
                int w = e1 - s1;
                for (int d = 1; d <= w; d++) cross |= (s2e[s1 + d] > e1);
                for (int d = 0; d < w; d++)  cross |= (e2s[s1 + d] < s1);
                myState = cross ? ST_REJ : ST_UND;
            }
        }
        seC[t] = (s1 << 12) | e1;
        cC[t]  = c1;
        stateA[t] = myState;
        int myB = s1 >> 5;

        // ---- bucket build (count, scan, fill) ----
        if (t < 64) bCnt[t] = 0;
        __syncthreads();
        if (myState == ST_UND) atomicAdd(&bCnt[myB], 1);
        __syncthreads();
        if (t == 0) {
            int run = 0;
            #pragma unroll
            for (int b = 0; b < 64; b++) { bOff[b] = run; bFill[b] = run; run += bCnt[b]; }
        }
        __syncthreads();
        if (myState == ST_UND) {
            int pos = atomicAdd(&bFill[myB], 1);
            bEntries[pos] = (short)t;
        }
        __syncthreads();

        // ---- rounds until no undecided ----
        while (true) {
            int und = __syncthreads_count(myState == ST_UND);
            if (und == 0) break;
            if (myState == ST_UND) {
                int bLo = (myB > 0) ? myB - 1 : 0;
                int bHi = (myB < 63) ? myB + 1 : 63;
                bool blocked = false, rejected = false;
                for (int bb = bLo; bb <= bHi && !rejected; bb++) {
                    int beg = bOff[bb], end = beg + bCnt[bb];
                    for (int q = beg; q < end; q++) {
                        int j = bEntries[q];
                        if (j >= t) continue;
                        int st = stateA[j];
                        if (st == ST_REJ) continue;
                        int se2 = seC[j];
                        if (spans_cross(s1, e1, se2 >> 12, se2 & 4095)) {
                            if (st == ST_ACC) { rejected = true; break; }
                            blocked = true;
                        }
                    }
                }
                if (rejected)      { myState = ST_REJ; stateA[t] = ST_REJ; }
                else if (!blocked) { myState = ST_ACC; stateA[t] = ST_ACC; }
            }
        }

        // ---- accepted: update tables for next chunk's prefilter ----
        bool accd = (myState == ST_ACC);
        if (accd) {
            atomicMax(&s2e[s1], e1);
            atomicMin(&e2s[e1], s1);
        }

        // ---- ordered compaction of accepts -> g_acc ----
        unsigned bal = __ballot_sync(FULL, accd);
        if (ln == 0) wCnt[wp] = __popc(bal);
        __syncthreads();
        if (t < 32) {
            int vv = wCnt[t], a2 = vv;
            #pragma unroll
            for (int o = 1; o < 32; o <<= 1) {
                int nb = __shfl_up_sync(FULL, a2, o);
                if (t >= o) a2 += nb;
            }
            wOff[t] = a2 - vv;
            if (t == 31) {
                sh_cnt = cnt0 + a2;
                if (cnt0 + a2 >= K) sh_done = 1;
            }
        }
        __syncthreads();
        if (accd) {
            int pos = cnt0 + wOff[wp] + __popc(bal & ltm);
            g_acc[pos] = ((unsigned long long)(s1 * T + e1) << 17) | (unsigned)c1;
        }
        __syncthreads();
    }

    // ---- finalize: first K accepts, bitonic by (s*T+e, idx), emit ----
    int cnt = sh_cnt;
    if (cnt > K) cnt = K;
    sortbuf[t] = (t < cnt) ? g_acc[t] : 0xFFFFFFFFFFFFFFFFull;
    __syncthreads();

    for (int ks = 2; ks <= NT; ks <<= 1) {
        for (int j = ks >> 1; j > 0; j >>= 1) {
            int ixj = t ^ j;
            if (ixj > t) {
                bool up = ((t & ks) == 0);
                unsigned long long a = sortbuf[t], b = sortbuf[ixj];
                if ((a > b) == up) { sortbuf[t] = b; sortbuf[ixj] = a; }
            }
            __syncthreads();
        }
    }

    int vcnt = (cnt < k_out) ? cnt : k_out;
    for (int j = t; j < k_out; j += NT) {
        bool valid = (j < vcnt);
        int c  = valid ? (int)(sortbuf[j] & 0x1FFFFull) : 0;
        float sc = valid ? scores[c] : 0.0f;
        int ss = valid ? spans[2 * c] : 0;
        int ee = valid ? spans[2 * c + 1] : 0;
        out[j]                     = sc;
        out[k_out + j]             = valid ? (float)c : 0.0f;
        out[2 * k_out + 2 * j]     = (float)ss;
        out[2 * k_out + 2 * j + 1] = (float)ee;
        out[4 * k_out + j]         = valid ? 1.0f : 0.0f;
    }
}

// ============================================================
// Launch: 6 nodes.
// ============================================================
extern "C" void kernel_launch(void* const* d_in, const int* in_sizes, int n_in,
                              void* d_out, int out_size) {
    const int*   spans  = (const int*)d_in[0];
    const float* scores = (const float*)d_in[1];
    const float* mask   = (const float*)d_in[2];
    const int*   pT     = (n_in > 3) ? (const int*)d_in[3] : nullptr;
    const int*   pK     = (n_in > 4) ? (const int*)d_in[4] : nullptr;
    int N = in_sizes[1];

    k_init_hist<<<NB, CHUNK>>>(scores, mask, N);
    k_scatter<<<NB, 256>>>(0, 1, N);   // A -> B
    k_scatter<<<NB, 256>>>(1, 0, N);   // B -> A
    k_scatter<<<NB, 256>>>(2, 1, N);   // A -> B
    k_scatter<<<NB, 256>>>(3, 0, N);   // B -> A  (sorted in g_bufA)
    k_greedy<<<1, NT>>>(spans, scores, pT, pK, N, (float*)d_out, out_size);
}